// round 1
// baseline (speedup 1.0000x reference)
#include <cuda_runtime.h>
#include <cuda_bf16.h>
#include <cub/block/block_radix_sort.cuh>
#include <cub/block/block_scan.cuh>

// Problem constants (from reference): N=256 rows, W=512 positions, 3 channels.
#define N_ROWS 256
#define WLEN   512
#define BT     128   // threads per block
#define IPT    4     // items per thread; BT*IPT == WLEN

// Per-(channel,row) partial losses. Device global scratch (no allocations allowed).
__device__ float g_partial[3 * N_ROWS];

// One CTA per (row, channel). Sorts the 512 heats (flag in LSB), then computes
//   S_pp = 2*sum over positives  v*(2r-1-p)   (r = rank among positives)
//   S_nn = 2*sum over negatives  v*(2s-1-q)
//   S_all= 2*sum over all        v*(2k-1-W)
// loss = S_pp/(p^2-p+1) + (1 - (S_all-S_pp-S_nn)/(2pq+1)) + S_nn/(q^2-q+1)
__global__ void __launch_bounds__(BT)
icl_channel_kernel(const float* __restrict__ a_gt, const float* __restrict__ s_gt,
                   const float* __restrict__ e_gt, const float* __restrict__ a_h,
                   const float* __restrict__ s_h,  const float* __restrict__ e_h)
{
    const int n = blockIdx.x;   // row
    const int c = blockIdx.y;   // channel 0..2
    const float* __restrict__ gt   = (c == 0) ? a_gt : (c == 1) ? s_gt : e_gt;
    const float* __restrict__ heat = (c == 0) ? a_h  : (c == 1) ? s_h  : e_h;
    const int tid = threadIdx.x;

    using Sorter = cub::BlockRadixSort<unsigned int, BT, IPT>;
    using ScanT  = cub::BlockScan<int, BT>;

    __shared__ union TempU {
        typename Sorter::TempStorage sort;
        typename ScanT::TempStorage  scan;
    } temp;
    __shared__ double s_red[3][BT / 32];

    // Load & pack keys: heats are uniform in [0,1) => float bits < 0x3F800000,
    // so (bits<<1)|flag is a 32-bit order-preserving key (value-major, flag LSB).
    unsigned int keys[IPT];
    const int base = n * WLEN;
    #pragma unroll
    for (int k = 0; k < IPT; ++k) {
        const int idx = tid * IPT + k;
        const float h = heat[base + idx];
        const unsigned int f = (gt[base + idx] > 0.5f) ? 1u : 0u;
        keys[k] = (__float_as_uint(h) << 1) | f;
    }

    Sorter(temp.sort).Sort(keys);     // ascending, blocked arrangement
    __syncthreads();                  // temp union reuse

    // Per-thread positive count among its 4 sorted items, then block scan
    int localPos = 0;
    #pragma unroll
    for (int k = 0; k < IPT; ++k) localPos += (int)(keys[k] & 1u);

    int prefix, p;
    ScanT(temp.scan).ExclusiveSum(localPos, prefix, p);  // prefix = positives before my items; p = total positives
    const int q = WLEN - p;

    // Weighted rank accumulation (fp64: weights up to ~511, sums up to ~9e4;
    // exact-rank math makes this match the analytic value to ~1e-12)
    double A_all = 0.0, A_pp = 0.0, A_nn = 0.0;
    int posBefore = prefix;
    #pragma unroll
    for (int k = 0; k < IPT; ++k) {
        const int kg = tid * IPT + k;                 // 0-indexed global rank
        const int f  = (int)(keys[k] & 1u);
        const double v = (double)__uint_as_float(keys[k] >> 1);
        A_all += v * (double)(2 * kg + 1 - WLEN);     // (2*(kg+1)-1-W)
        if (f) {
            const int r = posBefore + 1;              // 1-indexed rank among positives
            A_pp += v * (double)(2 * r - 1 - p);
            ++posBefore;
        } else {
            const int s = (kg - posBefore) + 1;       // 1-indexed rank among negatives
            A_nn += v * (double)(2 * s - 1 - q);
        }
    }

    // Block reduction of the three fp64 partials
    #pragma unroll
    for (int off = 16; off > 0; off >>= 1) {
        A_all += __shfl_down_sync(0xFFFFFFFFu, A_all, off);
        A_pp  += __shfl_down_sync(0xFFFFFFFFu, A_pp,  off);
        A_nn  += __shfl_down_sync(0xFFFFFFFFu, A_nn,  off);
    }
    const int wid = tid >> 5, lane = tid & 31;
    if (lane == 0) {
        s_red[0][wid] = A_all;
        s_red[1][wid] = A_pp;
        s_red[2][wid] = A_nn;
    }
    __syncthreads();

    if (tid == 0) {
        double Sa = 0.0, Sp = 0.0, Sn = 0.0;
        #pragma unroll
        for (int w = 0; w < BT / 32; ++w) {
            Sa += s_red[0][w]; Sp += s_red[1][w]; Sn += s_red[2][w];
        }
        Sa *= 2.0; Sp *= 2.0; Sn *= 2.0;
        const double pd = (double)p, qd = (double)q;
        const double c1 = Sp / (pd * (pd - 1.0) + 1.0);
        const double c2 = 1.0 - (Sa - Sp - Sn) / (2.0 * pd * qd + 1.0);
        const double c3 = Sn / (qd * (qd - 1.0) + 1.0);
        g_partial[c * N_ROWS + n] = (float)(c1 + c2 + c3);
    }
}

// Deterministic fold of the three channel partials (ALPHA == 1.0)
__global__ void icl_finalize_kernel(float* __restrict__ out)
{
    const int n = blockIdx.x * blockDim.x + threadIdx.x;
    if (n < N_ROWS)
        out[n] = g_partial[n] + g_partial[N_ROWS + n] + g_partial[2 * N_ROWS + n];
}

extern "C" void kernel_launch(void* const* d_in, const int* in_sizes, int n_in,
                              void* d_out, int out_size)
{
    const float* a_gt = (const float*)d_in[0];
    const float* s_gt = (const float*)d_in[1];
    const float* e_gt = (const float*)d_in[2];
    const float* a_h  = (const float*)d_in[3];
    const float* s_h  = (const float*)d_in[4];
    const float* e_h  = (const float*)d_in[5];
    float* out = (float*)d_out;

    dim3 grid(N_ROWS, 3);
    icl_channel_kernel<<<grid, BT>>>(a_gt, s_gt, e_gt, a_h, s_h, e_h);
    icl_finalize_kernel<<<1, N_ROWS>>>(out);
}

// round 2
// speedup vs baseline: 1.6061x; 1.6061x over previous
#include <cuda_runtime.h>
#include <cuda_bf16.h>

// N=256 rows, W=512 positions, 3 channels.
#define N_ROWS 256
#define WLEN   512
#define K      2048      // histogram buckets
#define BT     256       // threads per CTA
#define BPT    (K / BT)  // buckets per thread in scan (8)
#define NW     (BT / 32) // warps (8)

// One CTA per row. For each channel: counting-sort histogram (pos/neg packed
// counts + fixed-point value sums), packed prefix scan, then exact int64
// rank-weighted sums:
//   S_pp = 2*Σ_pos v*(2r-1-p),  S_nn = 2*Σ_neg v*(2s-1-q),  S_all = 2*Σ v*(2k-1-W)
// loss = S_pp/(p²-p+1) + (1 - (S_all-S_pp-S_nn)/(2pq+1)) + S_nn/(q²-q+1)
// Items within a bucket use the bucket's average rank (error ~1e-6 rel).
__global__ void __launch_bounds__(BT)
icl_row_kernel(const float* __restrict__ a_gt, const float* __restrict__ s_gt,
               const float* __restrict__ e_gt, const float* __restrict__ a_h,
               const float* __restrict__ s_h,  const float* __restrict__ e_h,
               float* __restrict__ out)
{
    __shared__ int                cnt[K];        // cntPos | cntNeg<<16
    __shared__ unsigned long long sv[2 * K];     // fixed-point (2^30) value sums: [0,K)=pos
    __shared__ int                warpAgg[NW];
    __shared__ long long          red[3][NW];

    const int n    = blockIdx.x;
    const int tid  = threadIdx.x;
    const int wid  = tid >> 5, lane = tid & 31;
    const int base = n * WLEN;

    const float* __restrict__ gts[3] = { a_gt, s_gt, e_gt };
    const float* __restrict__ hts[3] = { a_h,  s_h,  e_h  };

    double rowLoss = 0.0;  // only meaningful on tid 0

    #pragma unroll
    for (int c = 0; c < 3; ++c) {
        // ---- zero histogram ----
        #pragma unroll
        for (int i = tid; i < K; i += BT) cnt[i] = 0;
        #pragma unroll
        for (int i = tid; i < 2 * K; i += BT) sv[i] = 0ull;
        __syncthreads();

        // ---- histogram (each thread: 2 contiguous elements, coalesced) ----
        const float2 h2 = ((const float2*)(hts[c] + base))[tid];
        const float2 g2 = ((const float2*)(gts[c] + base))[tid];
        {
            const float h = h2.x;
            const bool  f = (g2.x > 0.5f);
            const int   b = (int)(h * (float)K);
            atomicAdd(&cnt[b], f ? 1 : (1 << 16));
            atomicAdd(&sv[(f ? 0 : K) + b], (unsigned long long)(h * 1073741824.0f));
        }
        {
            const float h = h2.y;
            const bool  f = (g2.y > 0.5f);
            const int   b = (int)(h * (float)K);
            atomicAdd(&cnt[b], f ? 1 : (1 << 16));
            atomicAdd(&sv[(f ? 0 : K) + b], (unsigned long long)(h * 1073741824.0f));
        }
        __syncthreads();

        // ---- packed exclusive scan over K buckets (blocked, BPT per thread) ----
        int cc[BPT];
        int tsum = 0;
        #pragma unroll
        for (int i = 0; i < BPT; ++i) { cc[i] = cnt[tid * BPT + i]; tsum += cc[i]; }

        int inc = tsum;
        #pragma unroll
        for (int off = 1; off < 32; off <<= 1) {
            const int v = __shfl_up_sync(0xFFFFFFFFu, inc, off);
            if (lane >= off) inc += v;
        }
        const int wexcl = inc - tsum;
        if (lane == 31) warpAgg[wid] = inc;
        __syncthreads();

        int wbase = 0, total = 0;
        #pragma unroll
        for (int w = 0; w < NW; ++w) {
            const int v = warpAgg[w];
            if (w < wid) wbase += v;
            total += v;
        }
        int prefix = wbase + wexcl;            // packed exclusive prefix (my 1st bucket)
        const int p = total & 0xFFFF;
        const int q = total >> 16;

        // ---- exact int64 rank-weighted accumulation ----
        long long app = 0, ann = 0, aall = 0;
        #pragma unroll
        for (int i = 0; i < BPT; ++i) {
            const int b   = tid * BPT + i;
            const int cpk = cc[i];
            if (cpk) {
                const int cP = cpk & 0xFFFF,   cN = cpk >> 16;
                const int PP = prefix & 0xFFFF, PN = prefix >> 16;
                const long long vP = (long long)sv[b];
                const long long vN = (long long)sv[K + b];
                app  += vP * (long long)(2 * PP + cP - p);
                ann  += vN * (long long)(2 * PN + cN - q);
                aall += (vP + vN) * (long long)(2 * (PP + PN) + cP + cN - WLEN);
            }
            prefix += cpk;
        }

        // ---- block reduce 3 × int64 ----
        #pragma unroll
        for (int off = 16; off > 0; off >>= 1) {
            app  += __shfl_down_sync(0xFFFFFFFFu, app,  off);
            ann  += __shfl_down_sync(0xFFFFFFFFu, ann,  off);
            aall += __shfl_down_sync(0xFFFFFFFFu, aall, off);
        }
        if (lane == 0) { red[0][wid] = app; red[1][wid] = ann; red[2][wid] = aall; }
        __syncthreads();

        if (tid == 0) {
            long long Ap = 0, An = 0, Aa = 0;
            #pragma unroll
            for (int w = 0; w < NW; ++w) { Ap += red[0][w]; An += red[1][w]; Aa += red[2][w]; }
            const double sc  = 2.0 / 1073741824.0;
            const double Spp = sc * (double)Ap;
            const double Snn = sc * (double)An;
            const double Sal = sc * (double)Aa;
            const double pd = (double)p, qd = (double)q;
            const double c1 = Spp / (pd * (pd - 1.0) + 1.0);
            const double c2 = 1.0 - (Sal - Spp - Snn) / (2.0 * pd * qd + 1.0);
            const double c3 = Snn / (qd * (qd - 1.0) + 1.0);
            rowLoss += c1 + c2 + c3;
        }
        __syncthreads();  // protect smem reuse before next channel's zeroing
    }

    if (tid == 0) out[n] = (float)rowLoss;
}

extern "C" void kernel_launch(void* const* d_in, const int* in_sizes, int n_in,
                              void* d_out, int out_size)
{
    const float* a_gt = (const float*)d_in[0];
    const float* s_gt = (const float*)d_in[1];
    const float* e_gt = (const float*)d_in[2];
    const float* a_h  = (const float*)d_in[3];
    const float* s_h  = (const float*)d_in[4];
    const float* e_h  = (const float*)d_in[5];
    float* out = (float*)d_out;

    icl_row_kernel<<<N_ROWS, BT>>>(a_gt, s_gt, e_gt, a_h, s_h, e_h, out);
}

// round 3
// speedup vs baseline: 2.0835x; 1.2973x over previous
#include <cuda_runtime.h>
#include <cuda_bf16.h>

// N=256 rows, W=512 positions, 3 channels, K=512 histogram buckets.
#define N_ROWS 256
#define WLEN   512
#define K      512
#define BT     512           // 1 element / thread / channel; 1 bucket / thread / channel
#define NW     (BT / 32)     // 16 warps

#define MASK40 ((1ull << 40) - 1ull)

// One CTA per row, all 3 channels concurrently.
// Per (channel, class∈{pos,neg}, bucket): one u64 = count<<40 | Σ round(h·2^30).
// After a packed prefix scan of counts, exact int64 rank-weighted sums give
//   S_pp = 2Σ_pos v(2r-1-p),  S_nn = 2Σ_neg v(2s-1-q),  S_all = 2Σ v(2k-1-W)
//   loss = S_pp/(p²-p+1) + (1 - (S_all-S_pp-S_nn)/(2pq+1)) + S_nn/(q²-q+1)
__global__ void __launch_bounds__(BT)
icl_row_kernel(const float* __restrict__ a_gt, const float* __restrict__ s_gt,
               const float* __restrict__ e_gt, const float* __restrict__ a_h,
               const float* __restrict__ s_h,  const float* __restrict__ e_h,
               float* __restrict__ out)
{
    __shared__ unsigned long long sv[3][2][K];   // [channel][pos=0/neg=1][bucket]
    __shared__ int       warpAgg[3][NW];
    __shared__ long long red[9][NW];
    __shared__ double    lossCh[3];

    const int n    = blockIdx.x;
    const int tid  = threadIdx.x;
    const int wid  = tid >> 5, lane = tid & 31;
    const int base = n * WLEN;

    const float* __restrict__ gts[3] = { a_gt, s_gt, e_gt };
    const float* __restrict__ hts[3] = { a_h,  s_h,  e_h  };

    // ---- zero histograms (3*2*512 = 3072 u64; 6 stores/thread) ----
    unsigned long long* svf = &sv[0][0][0];
    #pragma unroll
    for (int i = tid; i < 3 * 2 * K; i += BT) svf[i] = 0ull;
    __syncthreads();

    // ---- histogram: one element per thread per channel, one u64 atomic each ----
    #pragma unroll
    for (int c = 0; c < 3; ++c) {
        const float h = hts[c][base + tid];
        const int   f = (gts[c][base + tid] > 0.5f) ? 0 : 1;   // 0=pos,1=neg
        int b = (int)(h * (float)K);
        b = (b > K - 1) ? (K - 1) : b;
        const unsigned long long pk =
            (1ull << 40) | (unsigned long long)(unsigned int)(h * 1073741824.0f);
        atomicAdd(&sv[c][f][b], pk);
    }
    __syncthreads();

    // ---- per-channel packed count scan (bucket = tid) ----
    int x[3], inc[3];
    #pragma unroll
    for (int c = 0; c < 3; ++c) {
        const int cP = (int)(sv[c][0][tid] >> 40);
        const int cN = (int)(sv[c][1][tid] >> 40);
        x[c] = cP | (cN << 16);
        inc[c] = x[c];
    }
    #pragma unroll
    for (int off = 1; off < 32; off <<= 1) {
        #pragma unroll
        for (int c = 0; c < 3; ++c) {
            const int v = __shfl_up_sync(0xFFFFFFFFu, inc[c], off);
            if (lane >= off) inc[c] += v;
        }
    }
    if (lane == 31) {
        #pragma unroll
        for (int c = 0; c < 3; ++c) warpAgg[c][wid] = inc[c];
    }
    __syncthreads();

    long long acc[9];   // [c*3 + {pp,nn,all}]
    #pragma unroll
    for (int c = 0; c < 3; ++c) {
        int wbase = 0, total = 0;
        #pragma unroll
        for (int w = 0; w < NW; ++w) {
            const int v = warpAgg[c][w];
            if (w < wid) wbase += v;
            total += v;
        }
        const int prefix = wbase + inc[c] - x[c];   // packed exclusive prefix
        const int p  = total & 0xFFFF;
        const int q  = total >> 16;
        const int cP = x[c] & 0xFFFF, cN = x[c] >> 16;
        const int PP = prefix & 0xFFFF, PN = prefix >> 16;
        const long long vP = (long long)(sv[c][0][tid] & MASK40);
        const long long vN = (long long)(sv[c][1][tid] & MASK40);
        acc[c * 3 + 0] = vP * (long long)(2 * PP + cP - p);
        acc[c * 3 + 1] = vN * (long long)(2 * PN + cN - q);
        acc[c * 3 + 2] = (vP + vN) * (long long)(2 * (PP + PN) + cP + cN - WLEN);
        if (tid == 0) warpAgg[c][0] = total;  // stash packed totals for the tail
    }

    // ---- block reduce 9 × int64 ----
    #pragma unroll
    for (int off = 16; off > 0; off >>= 1) {
        #pragma unroll
        for (int j = 0; j < 9; ++j)
            acc[j] += __shfl_down_sync(0xFFFFFFFFu, acc[j], off);
    }
    if (lane == 0) {
        #pragma unroll
        for (int j = 0; j < 9; ++j) red[j][wid] = acc[j];
    }
    __syncthreads();

    // ---- final math: one thread per channel ----
    if (tid < 3) {
        const int c = tid;
        long long Ap = 0, An = 0, Aa = 0;
        #pragma unroll
        for (int w = 0; w < NW; ++w) {
            Ap += red[c * 3 + 0][w];
            An += red[c * 3 + 1][w];
            Aa += red[c * 3 + 2][w];
        }
        const int total = warpAgg[c][0];
        const double pd = (double)(total & 0xFFFF);
        const double qd = (double)(total >> 16);
        const double sc  = 2.0 / 1073741824.0;
        const double Spp = sc * (double)Ap;
        const double Snn = sc * (double)An;
        const double Sal = sc * (double)Aa;
        const double c1 = Spp / (pd * (pd - 1.0) + 1.0);
        const double c2 = 1.0 - (Sal - Spp - Snn) / (2.0 * pd * qd + 1.0);
        const double c3 = Snn / (qd * (qd - 1.0) + 1.0);
        lossCh[c] = c1 + c2 + c3;
    }
    __syncthreads();

    if (tid == 0) out[n] = (float)(lossCh[0] + lossCh[1] + lossCh[2]);
}

extern "C" void kernel_launch(void* const* d_in, const int* in_sizes, int n_in,
                              void* d_out, int out_size)
{
    const float* a_gt = (const float*)d_in[0];
    const float* s_gt = (const float*)d_in[1];
    const float* e_gt = (const float*)d_in[2];
    const float* a_h  = (const float*)d_in[3];
    const float* s_h  = (const float*)d_in[4];
    const float* e_h  = (const float*)d_in[5];
    float* out = (float*)d_out;

    icl_row_kernel<<<N_ROWS, BT>>>(a_gt, s_gt, e_gt, a_h, s_h, e_h, out);
}

// round 4
// speedup vs baseline: 2.4795x; 1.1901x over previous
#include <cuda_runtime.h>
#include <cuda_bf16.h>

// N=256 rows, W=512 positions, 3 channels, K=512 buckets.
#define N_ROWS 256
#define WLEN   512
#define K      512
#define BT     256           // 2 elements / thread; 2 buckets / thread
#define NW     (BT / 32)     // 8 warps

#define MASK40 ((1ull << 40) - 1ull)

// Cross-CTA combine scratch (device globals: no allocations allowed).
__device__ float        g_partial[N_ROWS * 3];
__device__ unsigned int g_cnt[N_ROWS];          // zero-init; atomicInc(...,2) self-resets

// One CTA per (row, channel). Counting-sort histogram into K buckets:
// one u64 per (class, bucket) = count<<40 | Σ round(h·2^30) (single smem atomic
// per element). Packed prefix scan of counts, then exact int64 rank-weighted sums:
//   S_pp = 2Σ_pos v(2r-1-p),  S_nn = 2Σ_neg v(2s-1-q),  S_all = 2Σ v(2k-1-W)
//   loss = S_pp/(p²-p+1) + (1-(S_all-S_pp-S_nn)/(2pq+1)) + S_nn/(q²-q+1)
// Last CTA of each row (fence + atomicInc) folds the 3 channel partials into out[n].
__global__ void __launch_bounds__(BT)
icl_kernel(const float* __restrict__ a_gt, const float* __restrict__ s_gt,
           const float* __restrict__ e_gt, const float* __restrict__ a_h,
           const float* __restrict__ s_h,  const float* __restrict__ e_h,
           float* __restrict__ out)
{
    __shared__ unsigned long long sv[2][K];   // [pos=0/neg=1][bucket]
    __shared__ int       warpAgg[NW];
    __shared__ long long red[3][NW];

    const int n    = blockIdx.x;
    const int c    = blockIdx.y;
    const int tid  = threadIdx.x;
    const int wid  = tid >> 5, lane = tid & 31;
    const int base = n * WLEN;

    const float* __restrict__ gt = (c == 0) ? a_gt : (c == 1) ? s_gt : e_gt;
    const float* __restrict__ ht = (c == 0) ? a_h  : (c == 1) ? s_h  : e_h;

    // ---- zero histogram (1024 u64; 4 stores/thread) ----
    unsigned long long* svf = &sv[0][0];
    #pragma unroll
    for (int i = tid; i < 2 * K; i += BT) svf[i] = 0ull;
    __syncthreads();

    // ---- histogram: 2 elements/thread (vectorized loads), 1 u64 atomic each ----
    const float2 h2 = ((const float2*)(ht + base))[tid];
    const float2 g2 = ((const float2*)(gt + base))[tid];
    {
        int b = (int)(h2.x * (float)K); b = (b > K - 1) ? (K - 1) : b;
        atomicAdd(&sv[(g2.x > 0.5f) ? 0 : 1][b],
                  (1ull << 40) | (unsigned long long)(unsigned int)(h2.x * 1073741824.0f));
    }
    {
        int b = (int)(h2.y * (float)K); b = (b > K - 1) ? (K - 1) : b;
        atomicAdd(&sv[(g2.y > 0.5f) ? 0 : 1][b],
                  (1ull << 40) | (unsigned long long)(unsigned int)(h2.y * 1073741824.0f));
    }
    __syncthreads();

    // ---- packed count scan over K buckets (2 buckets/thread, blocked) ----
    const int b0 = 2 * tid, b1 = 2 * tid + 1;
    const unsigned long long e00 = sv[0][b0], e10 = sv[1][b0];
    const unsigned long long e01 = sv[0][b1], e11 = sv[1][b1];
    const int x0 = (int)(e00 >> 40) | ((int)(e10 >> 40) << 16);
    const int x1 = (int)(e01 >> 40) | ((int)(e11 >> 40) << 16);
    const int tsum = x0 + x1;

    int incv = tsum;
    #pragma unroll
    for (int off = 1; off < 32; off <<= 1) {
        const int v = __shfl_up_sync(0xFFFFFFFFu, incv, off);
        if (lane >= off) incv += v;
    }
    if (lane == 31) warpAgg[wid] = incv;
    __syncthreads();

    int wbase = 0, total = 0;
    #pragma unroll
    for (int w = 0; w < NW; ++w) {
        const int v = warpAgg[w];
        if (w < wid) wbase += v;
        total += v;
    }
    int prefix = wbase + incv - tsum;    // packed exclusive prefix for bucket b0
    const int p = total & 0xFFFF;
    const int q = total >> 16;

    // ---- exact int64 rank-weighted accumulation (2 buckets) ----
    long long app = 0, ann = 0, aall = 0;
    {
        const int cP = x0 & 0xFFFF, cN = x0 >> 16;
        const int PP = prefix & 0xFFFF, PN = prefix >> 16;
        const long long vP = (long long)(e00 & MASK40);
        const long long vN = (long long)(e10 & MASK40);
        app  += vP * (long long)(2 * PP + cP - p);
        ann  += vN * (long long)(2 * PN + cN - q);
        aall += (vP + vN) * (long long)(2 * (PP + PN) + cP + cN - WLEN);
        prefix += x0;
    }
    {
        const int cP = x1 & 0xFFFF, cN = x1 >> 16;
        const int PP = prefix & 0xFFFF, PN = prefix >> 16;
        const long long vP = (long long)(e01 & MASK40);
        const long long vN = (long long)(e11 & MASK40);
        app  += vP * (long long)(2 * PP + cP - p);
        ann  += vN * (long long)(2 * PN + cN - q);
        aall += (vP + vN) * (long long)(2 * (PP + PN) + cP + cN - WLEN);
    }

    // ---- block reduce 3 × int64 ----
    #pragma unroll
    for (int off = 16; off > 0; off >>= 1) {
        app  += __shfl_down_sync(0xFFFFFFFFu, app,  off);
        ann  += __shfl_down_sync(0xFFFFFFFFu, ann,  off);
        aall += __shfl_down_sync(0xFFFFFFFFu, aall, off);
    }
    if (lane == 0) { red[0][wid] = app; red[1][wid] = ann; red[2][wid] = aall; }
    __syncthreads();

    // ---- fp32 tail + last-block combine ----
    if (tid == 0) {
        long long Ap = 0, An = 0, Aa = 0;
        #pragma unroll
        for (int w = 0; w < NW; ++w) { Ap += red[0][w]; An += red[1][w]; Aa += red[2][w]; }
        const long long Apn = Aa - Ap - An;        // exact: no cancellation risk
        const float sc = 2.0f / 1073741824.0f;
        const float pf = (float)p, qf = (float)q;
        const float c1 = (sc * (float)Ap)  / (pf * (pf - 1.0f) + 1.0f);
        const float c2 = 1.0f - (sc * (float)Apn) / (2.0f * pf * qf + 1.0f);
        const float c3 = (sc * (float)An)  / (qf * (qf - 1.0f) + 1.0f);

        g_partial[n * 3 + c] = c1 + c2 + c3;
        __threadfence();
        const unsigned int old = atomicInc(&g_cnt[n], 2u);   // wraps 2 -> 0 (replay-safe)
        if (old == 2u) {
            volatile float* gp = g_partial;
            out[n] = gp[n * 3 + 0] + gp[n * 3 + 1] + gp[n * 3 + 2];
        }
    }
}

extern "C" void kernel_launch(void* const* d_in, const int* in_sizes, int n_in,
                              void* d_out, int out_size)
{
    const float* a_gt = (const float*)d_in[0];
    const float* s_gt = (const float*)d_in[1];
    const float* e_gt = (const float*)d_in[2];
    const float* a_h  = (const float*)d_in[3];
    const float* s_h  = (const float*)d_in[4];
    const float* e_h  = (const float*)d_in[5];
    float* out = (float*)d_out;

    dim3 grid(N_ROWS, 3);
    icl_kernel<<<grid, BT>>>(a_gt, s_gt, e_gt, a_h, s_h, e_h, out);
}

// round 5
// speedup vs baseline: 3.0286x; 1.2214x over previous
#include <cuda_runtime.h>
#include <cuda_bf16.h>

// N=256 rows, W=512 positions, 3 channels, K=512 buckets.
#define N_ROWS 256
#define WLEN   512
#define K      512
#define BT     256           // 2 elements / thread; 2 buckets / thread
#define NW     (BT / 32)     // 8 warps

// Cross-CTA combine scratch (device globals: no allocations allowed).
__device__ float        g_partial[N_ROWS * 3];
__device__ unsigned int g_cnt[N_ROWS];          // zero-init; atomicInc(...,2) self-resets

// One CTA per (row, channel). Count-only histogram (packed pos|neg<<16, one
// 32-bit smem atomic per element), packed prefix scan, then each thread folds
// its own elements' exact int64 contributions using its bucket's (count,prefix):
//   item in bucket b (pos): v*(2*PP_b + cP_b - p)   [avg-rank identity]
//   S_pp = 2Σ..., S_nn = 2Σ..., S_all = 2Σ...; S_pn = S_all - S_pp - S_nn exact.
// loss = S_pp/(p²-p+1) + (1-S_pn/(2pq+1)) + S_nn/(q²-q+1)
// Last CTA of each row (fence + atomicInc) folds the 3 channel partials.
__global__ void __launch_bounds__(BT)
icl_kernel(const float* __restrict__ a_gt, const float* __restrict__ s_gt,
           const float* __restrict__ e_gt, const float* __restrict__ a_h,
           const float* __restrict__ s_h,  const float* __restrict__ e_h,
           float* __restrict__ out)
{
    __shared__ int       cnt[K];       // cntPos | cntNeg<<16
    __shared__ uint2     meta[K];      // {packed count, packed exclusive prefix}
    __shared__ int       warpAgg[NW];
    __shared__ long long red[3][NW];

    const int n    = blockIdx.x;
    const int c    = blockIdx.y;
    const int tid  = threadIdx.x;
    const int wid  = tid >> 5, lane = tid & 31;
    const int base = n * WLEN;

    const float* __restrict__ gt = (c == 0) ? a_gt : (c == 1) ? s_gt : e_gt;
    const float* __restrict__ ht = (c == 0) ? a_h  : (c == 1) ? s_h  : e_h;

    // ---- global loads first: DRAM latency hides under zero + sync ----
    const float2 h2 = ((const float2*)(ht + base))[tid];
    const float2 g2 = ((const float2*)(gt + base))[tid];

    // ---- zero count histogram (2 KB) ----
    cnt[tid]      = 0;
    cnt[tid + BT] = 0;
    __syncthreads();

    // ---- bucket + count-only atomics (32-bit) ----
    int bb0 = (int)(h2.x * (float)K); bb0 = (bb0 > K - 1) ? (K - 1) : bb0;
    int bb1 = (int)(h2.y * (float)K); bb1 = (bb1 > K - 1) ? (K - 1) : bb1;
    const bool f0 = (g2.x > 0.5f);
    const bool f1 = (g2.y > 0.5f);
    atomicAdd(&cnt[bb0], f0 ? 1 : (1 << 16));
    atomicAdd(&cnt[bb1], f1 ? 1 : (1 << 16));
    __syncthreads();

    // ---- packed count scan over K buckets (2 buckets/thread, blocked) ----
    const int x0 = cnt[2 * tid], x1 = cnt[2 * tid + 1];
    const int tsum = x0 + x1;

    int incv = tsum;
    #pragma unroll
    for (int off = 1; off < 32; off <<= 1) {
        const int v = __shfl_up_sync(0xFFFFFFFFu, incv, off);
        if (lane >= off) incv += v;
    }
    if (lane == 31) warpAgg[wid] = incv;
    __syncthreads();

    int wbase = 0, total = 0;
    #pragma unroll
    for (int w = 0; w < NW; ++w) {
        const int v = warpAgg[w];
        if (w < wid) wbase += v;
        total += v;
    }
    const int prefix = wbase + incv - tsum;      // packed exclusive prefix (bucket 2*tid)
    const int p = total & 0xFFFF;
    const int q = total >> 16;

    meta[2 * tid]     = make_uint2((unsigned)x0, (unsigned)prefix);
    meta[2 * tid + 1] = make_uint2((unsigned)x1, (unsigned)(prefix + x0));
    __syncthreads();

    // ---- per-element exact int64 contributions (no value atomics) ----
    long long app = 0, ann = 0, aall = 0;
    {
        const uint2 m = meta[bb0];
        const int cP = (int)(m.x & 0xFFFFu), cN = (int)(m.x >> 16);
        const int PP = (int)(m.y & 0xFFFFu), PN = (int)(m.y >> 16);
        const long long v = (long long)(int)(h2.x * 1073741824.0f);
        if (f0) app += v * (long long)(2 * PP + cP - p);
        else    ann += v * (long long)(2 * PN + cN - q);
        aall += v * (long long)(2 * (PP + PN) + (cP + cN) - WLEN);
    }
    {
        const uint2 m = meta[bb1];
        const int cP = (int)(m.x & 0xFFFFu), cN = (int)(m.x >> 16);
        const int PP = (int)(m.y & 0xFFFFu), PN = (int)(m.y >> 16);
        const long long v = (long long)(int)(h2.y * 1073741824.0f);
        if (f1) app += v * (long long)(2 * PP + cP - p);
        else    ann += v * (long long)(2 * PN + cN - q);
        aall += v * (long long)(2 * (PP + PN) + (cP + cN) - WLEN);
    }

    // ---- block reduce 3 × int64 ----
    #pragma unroll
    for (int off = 16; off > 0; off >>= 1) {
        app  += __shfl_down_sync(0xFFFFFFFFu, app,  off);
        ann  += __shfl_down_sync(0xFFFFFFFFu, ann,  off);
        aall += __shfl_down_sync(0xFFFFFFFFu, aall, off);
    }
    if (lane == 0) { red[0][wid] = app; red[1][wid] = ann; red[2][wid] = aall; }
    __syncthreads();

    // ---- fp32 tail + last-block combine ----
    if (tid == 0) {
        long long Ap = 0, An = 0, Aa = 0;
        #pragma unroll
        for (int w = 0; w < NW; ++w) { Ap += red[0][w]; An += red[1][w]; Aa += red[2][w]; }
        const long long Apn = Aa - Ap - An;        // exact: no cancellation risk
        const float sc = 2.0f / 1073741824.0f;
        const float pf = (float)p, qf = (float)q;
        const float c1 = (sc * (float)Ap)  / (pf * (pf - 1.0f) + 1.0f);
        const float c2 = 1.0f - (sc * (float)Apn) / (2.0f * pf * qf + 1.0f);
        const float c3 = (sc * (float)An)  / (qf * (qf - 1.0f) + 1.0f);

        g_partial[n * 3 + c] = c1 + c2 + c3;
        __threadfence();
        const unsigned int old = atomicInc(&g_cnt[n], 2u);   // wraps 2 -> 0 (replay-safe)
        if (old == 2u) {
            volatile float* gp = g_partial;
            out[n] = gp[n * 3 + 0] + gp[n * 3 + 1] + gp[n * 3 + 2];
        }
    }
}

extern "C" void kernel_launch(void* const* d_in, const int* in_sizes, int n_in,
                              void* d_out, int out_size)
{
    const float* a_gt = (const float*)d_in[0];
    const float* s_gt = (const float*)d_in[1];
    const float* e_gt = (const float*)d_in[2];
    const float* a_h  = (const float*)d_in[3];
    const float* s_h  = (const float*)d_in[4];
    const float* e_h  = (const float*)d_in[5];
    float* out = (float*)d_out;

    dim3 grid(N_ROWS, 3);
    icl_kernel<<<grid, BT>>>(a_gt, s_gt, e_gt, a_h, s_h, e_h, out);
}